// round 17
// baseline (speedup 1.0000x reference)
#include <cuda_runtime.h>
#include <cuda_bf16.h>
#include <cuda_fp16.h>
#include <cstdint>

#define SRC_LEN 256
#define TRG_LEN 256
#define BATCH   32
#define HID     512
#define ATT     128

// Scratch for projected activations. Layout: [(len_idx * BATCH + b) * ATT + a]
__device__ float g_enc_att[SRC_LEN * BATCH * ATT];
__device__ float g_dec_att[TRG_LEN * BATCH * ATT];

// Precomputed, pre-swizzled bf16 hi/lo W tiles: [z][chunk][16KB tile]
__device__ __align__(16) unsigned char g_wh[2][8][16384];
__device__ __align__(16) unsigned char g_wl[2][8][16384];

// Producer->consumer tile counters: [0]=enc half0, [1]=enc half1,
// [2]=dec half0, [3]=dec half1. Zeroed by prep_w each launch.
__device__ int g_cnt[4];

typedef unsigned int u32;
typedef unsigned long long u64;

__device__ __forceinline__ u32 smem_u32(const void* p) {
    u32 a; asm("{ .reg .u64 t; cvta.to.shared.u64 t, %1; cvt.u32.u64 %0, t; }"
               : "=r"(a) : "l"(p));
    return a;
}

#define LDSM_X4(rr, addr) \
    asm volatile("ldmatrix.sync.aligned.m8n8.x4.shared.b16 {%0,%1,%2,%3}, [%4];" \
        : "=r"((rr)[0]), "=r"((rr)[1]), "=r"((rr)[2]), "=r"((rr)[3]) : "r"(addr))

__device__ __forceinline__ void mma16816(float* d, const u32* a, const u32* b) {
    asm volatile(
        "mma.sync.aligned.m16n8k16.row.col.f32.bf16.bf16.f32 "
        "{%0,%1,%2,%3}, {%4,%5,%6,%7}, {%8,%9}, {%0,%1,%2,%3};"
        : "+f"(d[0]), "+f"(d[1]), "+f"(d[2]), "+f"(d[3])
        : "r"(a[0]), "r"(a[1]), "r"(a[2]), "r"(a[3]), "r"(b[0]), "r"(b[1]));
}

__device__ __forceinline__ void cp16(u32 smem_dst, const void* gsrc) {
    asm volatile("cp.async.cg.shared.global [%0], [%1], 16;"
                 :: "r"(smem_dst), "l"(gsrc) : "memory");
}
#define CP_COMMIT()  asm volatile("cp.async.commit_group;" ::: "memory")
#define CP_WAIT(n)   asm volatile("cp.async.wait_group %0;" :: "n"(n) : "memory")

// fp32 pair -> bf16 hi pair (truncate, via PRMT) + bf16 lo pair (residual, rn).
__device__ __forceinline__ void split2(float x0, float x1, u32& h2, u32& l2) {
    const u32 b0 = __float_as_uint(x0), b1 = __float_as_uint(x1);
    asm("prmt.b32 %0, %1, %2, 0x7632;" : "=r"(h2) : "r"(b0), "r"(b1));
    const float lf0 = x0 - __uint_as_float(b0 & 0xFFFF0000u);
    const float lf1 = x1 - __uint_as_float(b1 & 0xFFFF0000u);
    __nv_bfloat162 t = __float22bfloat162_rn(make_float2(lf0, lf1));
    l2 = *reinterpret_cast<u32*>(&t);
}
__device__ __forceinline__ void split_f4x2(const float4 v0, const float4 v1,
                                           uint4& H, uint4& L) {
    split2(v0.x, v0.y, H.x, L.x);
    split2(v0.z, v0.w, H.y, L.y);
    split2(v1.x, v1.y, H.z, L.z);
    split2(v1.z, v1.w, H.w, L.w);
}

__device__ __forceinline__ float tanh_fast(float x) {
    float y;
    asm("tanh.approx.f32 %0, %1;" : "=f"(y) : "f"(x));
    return y;
}

// =====================================================================
// prep_w: split W into bf16 hi/lo, pre-swizzled; also zero g_cnt.
// grid = (32 [chunk*4+slice], 2 z), 256 threads.
// =====================================================================
__global__ __launch_bounds__(256) void prep_w_kernel(
    const float* __restrict__ W_s, const float* __restrict__ W_t)
{
    if (blockIdx.x == 0 && blockIdx.y == 0 && threadIdx.x < 4)
        g_cnt[threadIdx.x] = 0;
    const int c = blockIdx.x >> 2;
    const int slice = blockIdx.x & 3;
    const int z = blockIdx.y;
    const float* __restrict__ W = z ? W_t : W_s;
    const int pu = slice * 256 + threadIdx.x;   // 0..1023 pair-units
    const int row = pu >> 3;                    // 0..127
    const int qq = (pu & 7) << 1;               // even float4 index
    const float* p = W + (size_t)row * HID + c * 64 + (qq << 2);
    const float4 v0 = *reinterpret_cast<const float4*>(p);
    const float4 v1 = *reinterpret_cast<const float4*>(p + 4);
    uint4 H, L; split_f4x2(v0, v1, H, L);
    const u32 off = (u32)(row * 128 + 16 * ((pu & 7) ^ (row & 7)));
    *reinterpret_cast<uint4*>(&g_wh[z][c][off]) = H;
    *reinterpret_cast<uint4*>(&g_wl[z][c][off]) = L;
}

// =====================================================================
// Fused kernel: bids [0,256) = proj producer blocks (scheduled first —
// in-order wave-1 dispatch guarantees producers precede consumers, so
// spin-waiting consumers can never starve producers).
// bids [256, 2304) = score consumer blocks gated on half-counters.
// 49152 B dynamic smem shared by both paths.
// Proj smem: AH 0..8K, AL 8K..16K, BH 16K..32K, BL 32K..48K (single stage).
// Score smem: sh_e[128][33] @0, sh_d[128][33] @16896, sh_v[128] @33792.
// =====================================================================
#define FSM_AH 0
#define FSM_AL 8192
#define FSM_BH 16384
#define FSM_BL 32768
#define FSM_TOTAL 49152

__global__ __launch_bounds__(256) void fused_kernel(
    const float* __restrict__ dec_out,
    const float* __restrict__ enc_outs,
    const float* __restrict__ b_t,
    const float* __restrict__ v_a,
    float* __restrict__ out)
{
    extern __shared__ char smem[];
    const int bid = blockIdx.x;
    const int tid = threadIdx.x;

    if (bid < 256) {
        // ================== PROJ PRODUCER ==================
        const u32 sb = smem_u32(smem);
        const u32 AHs = sb + FSM_AH, ALs = sb + FSM_AL;
        const u32 BHs = sb + FSM_BH, BLs = sb + FSM_BL;

        const int wid = tid >> 5;
        const int lane = tid & 31;
        const int tile = bid >> 1;
        const int z = bid & 1;
        const float* __restrict__ X = z ? dec_out : enc_outs;
        float* __restrict__ C = z ? g_dec_att : g_enc_att;
        const int m0 = tile * 64;

        const int j = lane >> 3;
        const int r = lane & 7;
        const int wm = wid & 1;        // m-group (x32)
        const int wn = wid >> 1;       // n-group (x32)

        const int rowA0 = wm * 32 + ((j & 1) << 3) + r;
        const int rowA1 = rowA0 + 16;
        const u32 offA0 = rowA0 * 128, cxA0 = (rowA0 & 7) * 16;
        const u32 offA1 = rowA1 * 128, cxA1 = (rowA1 & 7) * 16;
        const u32 kbAj = (u32)((j >> 1) << 4);

        u32 offB[2], cxB[2];
        #pragma unroll
        for (int p = 0; p < 2; p++) {
            const int nrow = wn * 32 + p * 16 + ((j >> 1) << 3) + r;
            offB[p] = nrow * 128;
            cxB[p]  = (nrow & 7) * 16;
        }
        const u32 kbBj = (u32)((j & 1) << 4);

        float d[2][4][4];
        #pragma unroll
        for (int mf = 0; mf < 2; mf++)
            #pragma unroll
            for (int nf = 0; nf < 4; nf++)
                #pragma unroll
                for (int q = 0; q < 4; q++) d[mf][nf][q] = 0.f;

        // Preload A raw values for chunk 0: 512 pair-units, 2 per thread.
        float4 areg[4];
        #pragma unroll
        for (int rr = 0; rr < 2; rr++) {
            const int pu = tid + rr * 256;
            const int row = pu >> 3;
            const int qq = (pu & 7) << 1;
            const float* p = X + (size_t)(m0 + row) * HID + (qq << 2);
            areg[2 * rr]     = *reinterpret_cast<const float4*>(p);
            areg[2 * rr + 1] = *reinterpret_cast<const float4*>(p + 4);
        }

        for (int c = 0; c < 8; c++) {
            __syncthreads();   // prior chunk's ldmatrix done; smem reusable

            // B: async copy of precomputed swizzled tiles (chunk c).
            {
                const unsigned char* sh = g_wh[z][c];
                const unsigned char* sl = g_wl[z][c];
                #pragma unroll
                for (int rr = 0; rr < 4; rr++) {
                    const u32 off = (u32)((tid + rr * 256) << 4);
                    cp16(BHs + off, sh + off);
                    cp16(BLs + off, sl + off);
                }
                CP_COMMIT();
            }
            // A: convert preloaded regs, STS.128.
            #pragma unroll
            for (int rr = 0; rr < 2; rr++) {
                const int pu = tid + rr * 256;
                const int row = pu >> 3;
                uint4 H, L; split_f4x2(areg[2 * rr], areg[2 * rr + 1], H, L);
                const u32 off = (u32)(row * 128 + 16 * ((pu & 7) ^ (row & 7)));
                *reinterpret_cast<uint4*>(smem + FSM_AH + off) = H;
                *reinterpret_cast<uint4*>(smem + FSM_AL + off) = L;
            }
            if (c < 7) {
                const int k0n = (c + 1) * 64;
                #pragma unroll
                for (int rr = 0; rr < 2; rr++) {
                    const int pu = tid + rr * 256;
                    const int row = pu >> 3;
                    const int qq = (pu & 7) << 1;
                    const float* p = X + (size_t)(m0 + row) * HID + k0n + (qq << 2);
                    areg[2 * rr]     = *reinterpret_cast<const float4*>(p);
                    areg[2 * rr + 1] = *reinterpret_cast<const float4*>(p + 4);
                }
            }
            CP_WAIT(0);
            __syncthreads();

            #pragma unroll
            for (int kk = 0; kk < 4; kk++) {
                const u32 kbA = (u32)(kk * 32) + kbAj;
                const u32 kbB = (u32)(kk * 32) + kbBj;

                u32 ah0[4], ah1[4], al0[4], al1[4];
                LDSM_X4(ah0, AHs + offA0 + (kbA ^ cxA0));
                LDSM_X4(ah1, AHs + offA1 + (kbA ^ cxA1));
                LDSM_X4(al0, ALs + offA0 + (kbA ^ cxA0));
                LDSM_X4(al1, ALs + offA1 + (kbA ^ cxA1));

                u32 bb[2][4];
                #pragma unroll
                for (int p = 0; p < 2; p++)
                    LDSM_X4(bb[p], BHs + offB[p] + (kbB ^ cxB[p]));
                #pragma unroll
                for (int p = 0; p < 2; p++) {
                    mma16816(d[0][2 * p],     ah0, &bb[p][0]);
                    mma16816(d[0][2 * p + 1], ah0, &bb[p][2]);
                    mma16816(d[1][2 * p],     ah1, &bb[p][0]);
                    mma16816(d[1][2 * p + 1], ah1, &bb[p][2]);
                    mma16816(d[0][2 * p],     al0, &bb[p][0]);
                    mma16816(d[0][2 * p + 1], al0, &bb[p][2]);
                    mma16816(d[1][2 * p],     al1, &bb[p][0]);
                    mma16816(d[1][2 * p + 1], al1, &bb[p][2]);
                }
                #pragma unroll
                for (int p = 0; p < 2; p++)
                    LDSM_X4(bb[p], BLs + offB[p] + (kbB ^ cxB[p]));
                #pragma unroll
                for (int p = 0; p < 2; p++) {
                    mma16816(d[0][2 * p],     ah0, &bb[p][0]);
                    mma16816(d[0][2 * p + 1], ah0, &bb[p][2]);
                    mma16816(d[1][2 * p],     ah1, &bb[p][0]);
                    mma16816(d[1][2 * p + 1], ah1, &bb[p][2]);
                }
            }
        }

        // Epilogue: bias + store, then release this tile.
        const int er = lane >> 2;
        const int ec = (lane & 3) << 1;
        float bias[4][2];
        #pragma unroll
        for (int nf = 0; nf < 4; nf++) {
            const int col = wn * 32 + nf * 8 + ec;
            bias[nf][0] = z ? b_t[col] : 0.f;
            bias[nf][1] = z ? b_t[col + 1] : 0.f;
        }
        #pragma unroll
        for (int mf = 0; mf < 2; mf++) {
            const int row = m0 + wm * 32 + mf * 16 + er;
            #pragma unroll
            for (int nf = 0; nf < 4; nf++) {
                const int col = wn * 32 + nf * 8 + ec;
                float2 v0; v0.x = d[mf][nf][0] + bias[nf][0]; v0.y = d[mf][nf][1] + bias[nf][1];
                *reinterpret_cast<float2*>(C + (size_t)row * ATT + col) = v0;
                float2 v1; v1.x = d[mf][nf][2] + bias[nf][0]; v1.y = d[mf][nf][3] + bias[nf][1];
                *reinterpret_cast<float2*>(C + (size_t)(row + 8) * ATT + col) = v1;
            }
        }
        __threadfence();       // each thread's stores globally visible
        __syncthreads();
        if (tid == 0)
            atomicAdd(&g_cnt[z * 2 + (tile >> 6)], 1);
        return;
    }

    // ================== SCORE CONSUMER ==================
    // Quadrant-ordered decode: qi 0..3, 512 blocks each (4 sx, 4 ty, 32 b).
    const int idx = bid - 256;
    const int qi = idx >> 9;
    const int rest = idx & 511;
    const int sx = (qi & 1) * 4 + (rest & 3);
    const int tq = (qi >> 1) * 4 + ((rest >> 2) & 3);
    const int b  = rest >> 4;
    const int s_base = sx * 32;
    const int t_base = tq * 32;

    // Wait for the enc/dec halves this tile reads.
    if (tid == 0) {
        const int ei = (s_base >> 7);       // enc half
        const int di = 2 + (t_base >> 7);   // dec half
        while (atomicAdd(&g_cnt[ei], 0) < 64) __nanosleep(128);
        while (atomicAdd(&g_cnt[di], 0) < 64) __nanosleep(128);
        __threadfence();
    }
    __syncthreads();

    float (*sh_e)[33] = reinterpret_cast<float(*)[33]>(smem);
    float (*sh_d)[33] = reinterpret_cast<float(*)[33]>(smem + 16896);
    float* sh_v = reinterpret_cast<float*>(smem + 33792);

    for (int u = tid; u < 32 * 32; u += 256) {
        const int i  = u >> 5;
        const int a4 = u & 31;
        const float4 ev = *reinterpret_cast<const float4*>(
            g_enc_att + ((size_t)(s_base + i) * BATCH + b) * ATT + (a4 << 2));
        sh_e[a4 * 4 + 0][i] = ev.x;
        sh_e[a4 * 4 + 1][i] = ev.y;
        sh_e[a4 * 4 + 2][i] = ev.z;
        sh_e[a4 * 4 + 3][i] = ev.w;
        const float4 dv = *reinterpret_cast<const float4*>(
            g_dec_att + ((size_t)(t_base + i) * BATCH + b) * ATT + (a4 << 2));
        sh_d[a4 * 4 + 0][i] = dv.x;
        sh_d[a4 * 4 + 1][i] = dv.y;
        sh_d[a4 * 4 + 2][i] = dv.z;
        sh_d[a4 * 4 + 3][i] = dv.w;
    }
    if (tid < ATT) sh_v[tid] = v_a[tid];
    __syncthreads();

    const int tx = tid & 15;
    const int ty = tid >> 4;
    const int sl = tx << 1;
    const int tl = ty << 1;

    float acc00 = 0.f, acc01 = 0.f, acc10 = 0.f, acc11 = 0.f;

    #pragma unroll 4
    for (int a = 0; a < ATT; a++) {
        const float va = sh_v[a];
        const float e0 = sh_e[a][sl];
        const float e1 = sh_e[a][sl + 1];
        const float d0 = sh_d[a][tl];
        const float d1 = sh_d[a][tl + 1];
        acc00 = fmaf(va, tanh_fast(d0 + e0), acc00);
        acc01 = fmaf(va, tanh_fast(d0 + e1), acc01);
        acc10 = fmaf(va, tanh_fast(d1 + e0), acc10);
        acc11 = fmaf(va, tanh_fast(d1 + e1), acc11);
    }

    const int tg = t_base + tl;
    const int sg = s_base + sl;
    float* o0 = out + ((size_t)tg * BATCH + b) * SRC_LEN + sg;
    float2 r0; r0.x = acc00; r0.y = acc01;
    *reinterpret_cast<float2*>(o0) = r0;
    float* o1 = o0 + (size_t)BATCH * SRC_LEN;
    float2 r1; r1.x = acc10; r1.y = acc11;
    *reinterpret_cast<float2*>(o1) = r1;
}

extern "C" void kernel_launch(void* const* d_in, const int* in_sizes, int n_in,
                              void* d_out, int out_size)
{
    const float* dec_out  = (const float*)d_in[0];  // (256, 32, 512)
    const float* enc_outs = (const float*)d_in[1];  // (256, 32, 512)
    const float* W_s      = (const float*)d_in[2];  // (128, 512)
    const float* W_t      = (const float*)d_in[3];  // (128, 512)
    const float* b_t      = (const float*)d_in[4];  // (128,)
    const float* v_a      = (const float*)d_in[5];  // (128, 1)
    float* out = (float*)d_out;                     // (256, 32, 256)

    (void)in_sizes; (void)n_in; (void)out_size;

    cudaFuncSetAttribute(fused_kernel,
                         cudaFuncAttributeMaxDynamicSharedMemorySize, FSM_TOTAL);

    prep_w_kernel<<<dim3(32, 2), 256>>>(W_s, W_t);
    fused_kernel<<<256 + 2048, 256, FSM_TOTAL>>>(dec_out, enc_outs, b_t, v_a, out);
}